// round 5
// baseline (speedup 1.0000x reference)
#include <cuda_runtime.h>
#include <cuda_fp16.h>
#include <math.h>
#include <stdint.h>

// Problem dims
#define Bsz  256
#define Tsz  256
#define INsz 4
#define HPsz 64
#define Esz  512
#define Hsz  1024
#define Dsz  4
#define ROWS (Bsz * Tsz)   // 65536

// ---------------------------------------------------------------------------
// Scratch (device globals; no allocation allowed)
// ---------------------------------------------------------------------------
__device__ float  g_x  [(size_t)ROWS * Esz];   // residual stream fp32
__device__ __half g_xhi[(size_t)ROWS * Esz];   // fp16 split of x (hi)
__device__ __half g_xlo[(size_t)ROWS * Esz];   // fp16 split of x (lo)
__device__ float  g_h1 [(size_t)ROWS * Hsz];   // GEMM1 out fp32
__device__ __half g_spk[(size_t)ROWS * Hsz];   // spikes fp16 (exact 0/1)
__device__ float  g_h2 [(size_t)ROWS * Esz];   // GEMM2 out fp32
// transposed fp16 weight splits: Wt1 [D][H][E], Wt2 [D][E][H]
__device__ __half g_w1hi[(size_t)Dsz * Hsz * Esz];
__device__ __half g_w1lo[(size_t)Dsz * Hsz * Esz];
__device__ __half g_w2hi[(size_t)Dsz * Esz * Hsz];
__device__ __half g_w2lo[(size_t)Dsz * Esz * Hsz];

// ---------------------------------------------------------------------------
// Helpers
// ---------------------------------------------------------------------------
__device__ __forceinline__ uint32_t sw128(uint32_t b) { return b ^ ((b >> 3) & 0x70); }

__device__ __forceinline__ uint32_t s2u(const void* p) {
    uint32_t a;
    asm("{ .reg .u64 t; cvta.to.shared.u64 t, %1; cvt.u32.u64 %0, t; }" : "=r"(a) : "l"(p));
    return a;
}

__device__ __forceinline__ void cp16(uint32_t saddr, const void* g) {
    asm volatile("cp.async.cg.shared.global [%0], [%1], 16;" :: "r"(saddr), "l"(g));
}

#define LDSM4(r0, r1, r2, r3, addr)                                           \
    asm volatile("ldmatrix.sync.aligned.m8n8.x4.shared.b16 {%0,%1,%2,%3}, [%4];" \
                 : "=r"(r0), "=r"(r1), "=r"(r2), "=r"(r3) : "r"(addr))

#define MMA16816(d, a, b)                                                     \
    asm volatile(                                                             \
        "mma.sync.aligned.m16n8k16.row.col.f32.f16.f16.f32 "                  \
        "{%0,%1,%2,%3},{%4,%5,%6,%7},{%8,%9},{%0,%1,%2,%3};"                  \
        : "+f"((d)[0]), "+f"((d)[1]), "+f"((d)[2]), "+f"((d)[3])              \
        : "r"((a)[0]), "r"((a)[1]), "r"((a)[2]), "r"((a)[3]),                 \
          "r"((b)[0]), "r"((b)[1]))

// ---------------------------------------------------------------------------
// Split+transpose weights: src [L][K][N] fp32 -> dst [L][N][K] fp16 hi/lo
// ---------------------------------------------------------------------------
__global__ void split_w(const float* __restrict__ W, __half* __restrict__ hi,
                        __half* __restrict__ lo, int K, int N) {
    int idx = blockIdx.x * blockDim.x + threadIdx.x;
    if (idx >= K * N) return;
    size_t lofs = (size_t)blockIdx.y * K * N;
    int k = idx / N, n = idx % N;
    float w = W[lofs + idx];
    __half h = __float2half_rn(w);
    hi[lofs + (size_t)n * K + k] = h;
    lo[lofs + (size_t)n * K + k] = __float2half_rn(w - __half2float(h));
}

// ---------------------------------------------------------------------------
// GEMM: C[M, Ntot] = Ahi@Bhi^T + Ahi@Blo^T (+ Alo@Bhi^T) + bias
// mma.sync m16n8k16, CTA 128x128, BK=64, 8 warps (4x2), 3-stage cp.async,
// fragment double-buffer, term-major MMA issue (no acc RAW chains)
// ---------------------------------------------------------------------------
template <int TERMS> struct Geo {
    static constexpr int OFF_ALO = 16384;                       // only if TERMS==3
    static constexpr int OFF_BHI = (TERMS == 3) ? 32768 : 16384;
    static constexpr int OFF_BLO = OFF_BHI + 16384;
    static constexpr int STG     = OFF_BLO + 16384;             // 64KB / 48KB
    static constexpr int TOT     = 3 * STG;
};

template <int TERMS>
__device__ __forceinline__ void load_stage(uint32_t sbase,
                                           const __half* A, const __half* Al,
                                           const __half* B, const __half* Bl,
                                           int K, int k0, int tid) {
#pragma unroll
    for (int it = 0; it < 4; it++) {
        int idx = tid + it * 256;
        int r = idx >> 3, c = idx & 7;
        uint32_t so = sw128((uint32_t)(r * 128 + c * 16));
        size_t go = (size_t)r * K + k0 + c * 8;
        cp16(sbase + so, A + go);
        if (TERMS == 3) cp16(sbase + Geo<TERMS>::OFF_ALO + so, Al + go);
        cp16(sbase + Geo<TERMS>::OFF_BHI + so, B + go);
        cp16(sbase + Geo<TERMS>::OFF_BLO + so, Bl + go);
    }
    asm volatile("cp.async.commit_group;" ::: "memory");
}

template <int TERMS>
__device__ __forceinline__ void load_frags(uint32_t stg, int ks,
                                           int warp_m, int warp_n, int lane,
                                           uint32_t (&ahi)[2][4], uint32_t (&alo)[2][4],
                                           uint32_t (&bhi)[8][2], uint32_t (&blo)[8][2]) {
    int row_in = lane & 7, grp = lane >> 3;
#pragma unroll
    for (int mf = 0; mf < 2; mf++) {
        int r = warp_m * 32 + mf * 16 + (grp & 1) * 8 + row_in;
        int kb = ks * 32 + (grp >> 1) * 16;
        uint32_t off = sw128((uint32_t)(r * 128 + kb));
        LDSM4(ahi[mf][0], ahi[mf][1], ahi[mf][2], ahi[mf][3], stg + off);
        if (TERMS == 3)
            LDSM4(alo[mf][0], alo[mf][1], alo[mf][2], alo[mf][3],
                  stg + Geo<TERMS>::OFF_ALO + off);
    }
#pragma unroll
    for (int p = 0; p < 4; p++) {
        int r = warp_n * 64 + p * 16 + (grp >> 1) * 8 + row_in;
        int kb = ks * 32 + (grp & 1) * 16;
        uint32_t off = sw128((uint32_t)(r * 128 + kb));
        uint32_t t0, t1, t2, t3;
        LDSM4(t0, t1, t2, t3, stg + Geo<TERMS>::OFF_BHI + off);
        bhi[2 * p][0] = t0; bhi[2 * p][1] = t1;
        bhi[2 * p + 1][0] = t2; bhi[2 * p + 1][1] = t3;
        LDSM4(t0, t1, t2, t3, stg + Geo<TERMS>::OFF_BLO + off);
        blo[2 * p][0] = t0; blo[2 * p][1] = t1;
        blo[2 * p + 1][0] = t2; blo[2 * p + 1][1] = t3;
    }
}

template <int TERMS>
__global__ void __launch_bounds__(256, 1)
gemm_hs(const __half* __restrict__ Ahi, const __half* __restrict__ Alo,
        const __half* __restrict__ Bhi, const __half* __restrict__ Blo,
        const float* __restrict__ bias, float* __restrict__ C,
        int Ntot, int K) {
    extern __shared__ char smc[];
    uint32_t sb = s2u(smc);
    int tid = threadIdx.x;
    int wid = tid >> 5, lane = tid & 31;
    int warp_m = wid >> 1, warp_n = wid & 1;
    int bx = blockIdx.x, by = blockIdx.y;

    const __half* Ah = Ahi + (size_t)(by * 128) * K;
    const __half* Al = Alo + (size_t)(by * 128) * K;
    const __half* Bh = Bhi + (size_t)(bx * 128) * K;
    const __half* Bl = Blo + (size_t)(bx * 128) * K;

    const int NC = K / 64;
    float acc[2][8][4] = {};
    uint32_t ahi[2][2][4], alo[2][2][4], bhi[2][8][2], blo[2][8][2];

    // prologue: 2 stages in flight
    load_stage<TERMS>(sb + 0 * Geo<TERMS>::STG, Ah, Al, Bh, Bl, K, 0, tid);
    load_stage<TERMS>(sb + 1 * Geo<TERMS>::STG, Ah, Al, Bh, Bl, K, 64, tid);

    int sc = 0;  // stage of chunk c (mod 3)
    for (int c = 0; c < NC; c++) {
        uint32_t stg = sb + sc * Geo<TERMS>::STG;
        if (c + 1 < NC)
            asm volatile("cp.async.wait_group 1;" ::: "memory");
        else
            asm volatile("cp.async.wait_group 0;" ::: "memory");
        __syncthreads();
        if (c + 2 < NC) {
            int sn = sc - 1; if (sn < 0) sn += 3;   // (sc+2)%3
            load_stage<TERMS>(sb + sn * Geo<TERMS>::STG, Ah, Al, Bh, Bl, K, (c + 2) * 64, tid);
        }

        load_frags<TERMS>(stg, 0, warp_m, warp_n, lane, ahi[0], alo[0], bhi[0], blo[0]);
#pragma unroll
        for (int ks = 0; ks < 4; ks++) {
            int cur = ks & 1, nxt = cur ^ 1;
            if (ks < 3)
                load_frags<TERMS>(stg, ks + 1, warp_m, warp_n, lane,
                                  ahi[nxt], alo[nxt], bhi[nxt], blo[nxt]);
            // term-major: no back-to-back same-accumulator MMAs
#pragma unroll
            for (int mf = 0; mf < 2; mf++)
#pragma unroll
                for (int nf = 0; nf < 8; nf++)
                    MMA16816(acc[mf][nf], ahi[cur][mf], bhi[cur][nf]);
#pragma unroll
            for (int mf = 0; mf < 2; mf++)
#pragma unroll
                for (int nf = 0; nf < 8; nf++)
                    MMA16816(acc[mf][nf], ahi[cur][mf], blo[cur][nf]);
            if (TERMS == 3) {
#pragma unroll
                for (int mf = 0; mf < 2; mf++)
#pragma unroll
                    for (int nf = 0; nf < 8; nf++)
                        MMA16816(acc[mf][nf], alo[cur][mf], bhi[cur][nf]);
            }
        }
        sc++; if (sc == 3) sc = 0;
    }

    // Epilogue: fused bias, fp32 float2 stores
    int col_base = bx * 128 + warp_n * 64 + (lane & 3) * 2;
    int row_base = by * 128 + warp_m * 32 + (lane >> 2);
    float bsr[8][2];
#pragma unroll
    for (int nf = 0; nf < 8; nf++) {
        bsr[nf][0] = __ldg(bias + col_base + nf * 8);
        bsr[nf][1] = __ldg(bias + col_base + nf * 8 + 1);
    }
#pragma unroll
    for (int mf = 0; mf < 2; mf++)
#pragma unroll
        for (int nf = 0; nf < 8; nf++) {
            int col = col_base + nf * 8;
            int r0 = row_base + mf * 16;
            float2 v0 = { acc[mf][nf][0] + bsr[nf][0], acc[mf][nf][1] + bsr[nf][1] };
            float2 v1 = { acc[mf][nf][2] + bsr[nf][0], acc[mf][nf][3] + bsr[nf][1] };
            *(float2*)(C + (size_t)r0 * Ntot + col) = v0;
            *(float2*)(C + (size_t)(r0 + 8) * Ntot + col) = v1;
        }
}

// ---------------------------------------------------------------------------
// Input projector: x = gelu(hist @ W1 + b1) @ W2 + b2, plus fp16 hi/lo of x
// ---------------------------------------------------------------------------
__global__ void proj_kernel(const float* __restrict__ hist,
                            const float* __restrict__ W1, const float* __restrict__ b1,
                            const float* __restrict__ W2, const float* __restrict__ b2,
                            float* __restrict__ out,
                            __half* __restrict__ ohi, __half* __restrict__ olo) {
    __shared__ float inr[INsz];
    __shared__ float hp[HPsz];
    int row = blockIdx.x;
    int tid = threadIdx.x;

    if (tid < INsz) inr[tid] = hist[(size_t)row * INsz + tid];
    __syncthreads();

    if (tid < HPsz) {
        float a = b1[tid];
#pragma unroll
        for (int i = 0; i < INsz; i++) a += inr[i] * W1[i * HPsz + tid];
        hp[tid] = 0.5f * a * (1.0f + erff(a * 0.70710678118654752440f));
    }
    __syncthreads();

    for (int o = tid; o < Esz; o += 128) {
        float a = b2[o];
#pragma unroll 8
        for (int j = 0; j < HPsz; j++) a += hp[j] * W2[j * Esz + o];
        size_t off = (size_t)row * Esz + o;
        out[off] = a;
        __half h = __float2half_rn(a);
        ohi[off] = h;
        olo[off] = __float2half_rn(a - __half2float(h));
    }
}

// ---------------------------------------------------------------------------
// Block reduce
// ---------------------------------------------------------------------------
__device__ __forceinline__ float block_reduce_sum(float v) {
    __shared__ float smr[32];
    int lane = threadIdx.x & 31, wid = threadIdx.x >> 5;
#pragma unroll
    for (int o = 16; o > 0; o >>= 1) v += __shfl_xor_sync(0xffffffffu, v, o);
    __syncthreads();
    if (lane == 0) smr[wid] = v;
    __syncthreads();
    if (wid == 0) {
        v = (lane < (int)(blockDim.x >> 5)) ? smr[lane] : 0.0f;
#pragma unroll
        for (int o = 16; o > 0; o >>= 1) v += __shfl_xor_sync(0xffffffffu, v, o);
        if (lane == 0) smr[0] = v;
    }
    __syncthreads();
    return smr[0];
}

// ---------------------------------------------------------------------------
// Fused LayerNorm + LIF (spike emit). One block per batch; membrane in regs.
// h: [B,T,H] fp32 (GEMM1 out), spk: [B,T,H] fp16 {0,1}
// 256 threads, float4/thread (H=1024). Next-row prefetch hides load latency.
// ---------------------------------------------------------------------------
__global__ void __launch_bounds__(256, 2)
ln_lif_fused(const float* __restrict__ h, const float* __restrict__ gamma,
             const float* __restrict__ beta, __half* __restrict__ spk) {
    int b = blockIdx.x, tid = threadIdx.x;
    const int NT = Hsz / 4;   // 256 float4 per row
    float4 g4 = ((const float4*)gamma)[tid];
    float4 b4 = ((const float4*)beta)[tid];
    const float4* hp = (const float4*)(h + (size_t)b * Tsz * Hsz);
    uint2* sp = (uint2*)(spk + (size_t)b * Tsz * Hsz);

    float4 vm = {0.f, 0.f, 0.f, 0.f};
    float4 cur = hp[tid];
    for (int t = 0; t < Tsz; t++) {
        float4 nxt = cur;
        if (t + 1 < Tsz) nxt = hp[(t + 1) * NT + tid];

        float s = cur.x + cur.y + cur.z + cur.w;
        float m = block_reduce_sum(s) * (1.0f / Hsz);
        float dx = cur.x - m, dy = cur.y - m, dz = cur.z - m, dw = cur.w - m;
        float var = block_reduce_sum(dx * dx + dy * dy + dz * dz + dw * dw) * (1.0f / Hsz);
        float inv = 1.0f / sqrtf(var + 1e-5f);

        float n0 = dx * inv * g4.x + b4.x;
        float n1 = dy * inv * g4.y + b4.y;
        float n2 = dz * inv * g4.z + b4.z;
        float n3 = dw * inv * g4.w + b4.w;

        vm.x = vm.x + (n0 - vm.x) * 0.5f;
        vm.y = vm.y + (n1 - vm.y) * 0.5f;
        vm.z = vm.z + (n2 - vm.z) * 0.5f;
        vm.w = vm.w + (n3 - vm.w) * 0.5f;
        float s0 = 0.f, s1 = 0.f, s2 = 0.f, s3 = 0.f;
        if (vm.x >= 1.0f) { s0 = 1.0f; vm.x = 0.f; }
        if (vm.y >= 1.0f) { s1 = 1.0f; vm.y = 0.f; }
        if (vm.z >= 1.0f) { s2 = 1.0f; vm.z = 0.f; }
        if (vm.w >= 1.0f) { s3 = 1.0f; vm.w = 0.f; }

        __half2 lo2 = __halves2half2(__float2half_rn(s0), __float2half_rn(s1));
        __half2 hi2 = __halves2half2(__float2half_rn(s2), __float2half_rn(s3));
        uint2 pack = { *(uint32_t*)&lo2, *(uint32_t*)&hi2 };
        sp[t * (Hsz / 4) + tid] = pack;

        cur = nxt;
    }
}

// ---------------------------------------------------------------------------
// Fused LayerNorm + LIF + residual add + sparse split refresh.
// h: [B,T,E] fp32 (GEMM2 out). On spike: x += 1, refresh xhi/xlo (else
// unchanged values keep their stored split — value-identical skip).
// 128 threads, float4/thread (E=512).
// ---------------------------------------------------------------------------
__global__ void __launch_bounds__(128, 4)
ln_lifadd_fused(const float* __restrict__ h, const float* __restrict__ gamma,
                const float* __restrict__ beta, float* __restrict__ x,
                __half* __restrict__ xhi, __half* __restrict__ xlo) {
    int b = blockIdx.x, tid = threadIdx.x;
    const int NT = Esz / 4;   // 128 float4 per row
    float4 g4 = ((const float4*)gamma)[tid];
    float4 b4 = ((const float4*)beta)[tid];
    const float4* hp = (const float4*)(h + (size_t)b * Tsz * Esz);
    size_t xrow = (size_t)b * Tsz * Esz + tid * 4;

    float4 vm = {0.f, 0.f, 0.f, 0.f};
    float4 cur = hp[tid];
    for (int t = 0; t < Tsz; t++) {
        float4 nxt = cur;
        if (t + 1 < Tsz) nxt = hp[(t + 1) * NT + tid];

        float s = cur.x + cur.y + cur.z + cur.w;
        float m = block_reduce_sum(s) * (1.0f / Esz);
        float dx = cur.x - m, dy = cur.y - m, dz = cur.z - m, dw = cur.w - m;
        float var = block_reduce_sum(dx * dx + dy * dy + dz * dz + dw * dw) * (1.0f / Esz);
        float inv = 1.0f / sqrtf(var + 1e-5f);

        float n0 = dx * inv * g4.x + b4.x;
        float n1 = dy * inv * g4.y + b4.y;
        float n2 = dz * inv * g4.z + b4.z;
        float n3 = dw * inv * g4.w + b4.w;

        size_t o = xrow + (size_t)t * Esz;
        vm.x = vm.x + (n0 - vm.x) * 0.5f;
        vm.y = vm.y + (n1 - vm.y) * 0.5f;
        vm.z = vm.z + (n2 - vm.z) * 0.5f;
        vm.w = vm.w + (n3 - vm.w) * 0.5f;
#pragma unroll
        for (int cidx = 0; cidx < 4; cidx++) {
            float* vptr = (cidx == 0) ? &vm.x : (cidx == 1) ? &vm.y : (cidx == 2) ? &vm.z : &vm.w;
            if (*vptr >= 1.0f) {
                *vptr = 0.f;
                float xv = x[o + cidx] + 1.0f;
                x[o + cidx] = xv;
                __half hh = __float2half_rn(xv);
                xhi[o + cidx] = hh;
                xlo[o + cidx] = __float2half_rn(xv - __half2float(hh));
            }
        }
        cur = nxt;
    }
}

// Extract last timestep
__global__ void last_kernel(const float* __restrict__ x, float* __restrict__ out) {
    int i = blockIdx.x * blockDim.x + threadIdx.x;
    if (i < Bsz * Esz) {
        int b = i / Esz, e = i % Esz;
        out[i] = x[((size_t)b * Tsz + (Tsz - 1)) * Esz + e];
    }
}

// ---------------------------------------------------------------------------
extern "C" void kernel_launch(void* const* d_in, const int* in_sizes, int n_in,
                              void* d_out, int out_size) {
    const float* hist  = (const float*)d_in[0];
    const float* pW1   = (const float*)d_in[1];
    const float* pb1   = (const float*)d_in[2];
    const float* pW2   = (const float*)d_in[3];
    const float* pb2   = (const float*)d_in[4];
    const float* fc1_w = (const float*)d_in[5];
    const float* fc1_b = (const float*)d_in[6];
    const float* ln1_g = (const float*)d_in[7];
    const float* ln1_b = (const float*)d_in[8];
    const float* fc2_w = (const float*)d_in[9];
    const float* fc2_b = (const float*)d_in[10];
    const float* ln2_g = (const float*)d_in[11];
    const float* ln2_b = (const float*)d_in[12];

    float *x, *h1, *h2;
    __half *xhi, *xlo, *spk, *w1hi, *w1lo, *w2hi, *w2lo;
    cudaGetSymbolAddress((void**)&x,    g_x);
    cudaGetSymbolAddress((void**)&h1,   g_h1);
    cudaGetSymbolAddress((void**)&h2,   g_h2);
    cudaGetSymbolAddress((void**)&xhi,  g_xhi);
    cudaGetSymbolAddress((void**)&xlo,  g_xlo);
    cudaGetSymbolAddress((void**)&spk,  g_spk);
    cudaGetSymbolAddress((void**)&w1hi, g_w1hi);
    cudaGetSymbolAddress((void**)&w1lo, g_w1lo);
    cudaGetSymbolAddress((void**)&w2hi, g_w2hi);
    cudaGetSymbolAddress((void**)&w2lo, g_w2lo);

    cudaFuncSetAttribute(gemm_hs<3>, cudaFuncAttributeMaxDynamicSharedMemorySize, Geo<3>::TOT);
    cudaFuncSetAttribute(gemm_hs<2>, cudaFuncAttributeMaxDynamicSharedMemorySize, Geo<2>::TOT);

    split_w<<<dim3((Esz * Hsz + 255) / 256, Dsz), 256>>>(fc1_w, w1hi, w1lo, Esz, Hsz);
    split_w<<<dim3((Hsz * Esz + 255) / 256, Dsz), 256>>>(fc2_w, w2hi, w2lo, Hsz, Esz);

    proj_kernel<<<ROWS, 128>>>(hist, pW1, pb1, pW2, pb2, x, xhi, xlo);

    for (int d = 0; d < Dsz; d++) {
        size_t o1 = (size_t)d * Hsz * Esz;   // Wt1 [H][E] per layer
        size_t o2 = (size_t)d * Esz * Hsz;   // Wt2 [E][H] per layer

        gemm_hs<3><<<dim3(Hsz / 128, ROWS / 128), 256, Geo<3>::TOT>>>(
            xhi, xlo, w1hi + o1, w1lo + o1, fc1_b + d * Hsz, h1, Hsz, Esz);
        ln_lif_fused<<<Bsz, 256>>>(h1, ln1_g + d * Hsz, ln1_b + d * Hsz, spk);

        gemm_hs<2><<<dim3(Esz / 128, ROWS / 128), 256, Geo<2>::TOT>>>(
            spk, spk, w2hi + o2, w2lo + o2, fc2_b + d * Esz, h2, Esz, Hsz);
        ln_lifadd_fused<<<Bsz, 128>>>(h2, ln2_g + d * Esz, ln2_b + d * Esz, x, xhi, xlo);
    }

    last_kernel<<<(Bsz * Esz + 255) / 256, 256>>>(x, (float*)d_out);
}

// round 6
// speedup vs baseline: 1.0394x; 1.0394x over previous
#include <cuda_runtime.h>
#include <cuda_fp16.h>
#include <math.h>
#include <stdint.h>

// Problem dims
#define Bsz  256
#define Tsz  256
#define INsz 4
#define HPsz 64
#define Esz  512
#define Hsz  1024
#define Dsz  4
#define ROWS (Bsz * Tsz)   // 65536

// ---------------------------------------------------------------------------
// Scratch (device globals; no allocation allowed)
// ---------------------------------------------------------------------------
__device__ float  g_x  [(size_t)ROWS * Esz];   // residual stream fp32
__device__ __half g_xhi[(size_t)ROWS * Esz];   // fp16 split of x (hi)
__device__ __half g_xlo[(size_t)ROWS * Esz];   // fp16 split of x (lo)
__device__ float  g_h1 [(size_t)ROWS * Hsz];   // GEMM1 out fp32
__device__ __half g_spk[(size_t)ROWS * Hsz];   // spikes fp16 (exact 0/1)
__device__ float  g_h2 [(size_t)ROWS * Esz];   // GEMM2 out fp32
__device__ float  g_mean[ROWS];                // LN row mean
__device__ float  g_rstd[ROWS];                // LN row inv-std
// transposed fp16 weight splits: Wt1 [D][H][E], Wt2 [D][E][H]
__device__ __half g_w1hi[(size_t)Dsz * Hsz * Esz];
__device__ __half g_w1lo[(size_t)Dsz * Hsz * Esz];
__device__ __half g_w2hi[(size_t)Dsz * Esz * Hsz];
__device__ __half g_w2lo[(size_t)Dsz * Esz * Hsz];

// ---------------------------------------------------------------------------
// Helpers
// ---------------------------------------------------------------------------
__device__ __forceinline__ uint32_t sw128(uint32_t b) { return b ^ ((b >> 3) & 0x70); }

__device__ __forceinline__ uint32_t s2u(const void* p) {
    uint32_t a;
    asm("{ .reg .u64 t; cvta.to.shared.u64 t, %1; cvt.u32.u64 %0, t; }" : "=r"(a) : "l"(p));
    return a;
}

__device__ __forceinline__ void cp16(uint32_t saddr, const void* g) {
    asm volatile("cp.async.cg.shared.global [%0], [%1], 16;" :: "r"(saddr), "l"(g));
}

#define LDSM4(r0, r1, r2, r3, addr)                                           \
    asm volatile("ldmatrix.sync.aligned.m8n8.x4.shared.b16 {%0,%1,%2,%3}, [%4];" \
                 : "=r"(r0), "=r"(r1), "=r"(r2), "=r"(r3) : "r"(addr))

#define MMA16816(d, a, b)                                                     \
    asm volatile(                                                             \
        "mma.sync.aligned.m16n8k16.row.col.f32.f16.f16.f32 "                  \
        "{%0,%1,%2,%3},{%4,%5,%6,%7},{%8,%9},{%0,%1,%2,%3};"                  \
        : "+f"((d)[0]), "+f"((d)[1]), "+f"((d)[2]), "+f"((d)[3])              \
        : "r"((a)[0]), "r"((a)[1]), "r"((a)[2]), "r"((a)[3]),                 \
          "r"((b)[0]), "r"((b)[1]))

// ---------------------------------------------------------------------------
// Split+transpose weights: src [L][K][N] fp32 -> dst [L][N][K] fp16 hi/lo
// ---------------------------------------------------------------------------
__global__ void split_w(const float* __restrict__ W, __half* __restrict__ hi,
                        __half* __restrict__ lo, int K, int N) {
    int idx = blockIdx.x * blockDim.x + threadIdx.x;
    if (idx >= K * N) return;
    size_t lofs = (size_t)blockIdx.y * K * N;
    int k = idx / N, n = idx % N;
    float w = W[lofs + idx];
    __half h = __float2half_rn(w);
    hi[lofs + (size_t)n * K + k] = h;
    lo[lofs + (size_t)n * K + k] = __float2half_rn(w - __half2float(h));
}

// ---------------------------------------------------------------------------
// GEMM: C[M, Ntot] = Ahi@Bhi^T + Ahi@Blo^T (+ Alo@Bhi^T) + bias
// mma.sync m16n8k16, CTA 128x128, BK=64, 8 warps (4x2), 3-stage cp.async.
// Each CTA processes TILES consecutive N-tiles with a CONTINUOUS pipeline
// (one prologue per CTA; epilogues overlap next tile's loads).
// ---------------------------------------------------------------------------
template <int TERMS> struct Geo {
    static constexpr int OFF_ALO = 16384;
    static constexpr int OFF_BHI = (TERMS == 3) ? 32768 : 16384;
    static constexpr int OFF_BLO = OFF_BHI + 16384;
    static constexpr int STG     = OFF_BLO + 16384;   // 64KB / 48KB
    static constexpr int TOT     = 3 * STG;
};

template <int TERMS, int KK>
__device__ __forceinline__ void load_stage(uint32_t sbase,
                                           const __half* A, const __half* Al,
                                           const __half* B, const __half* Bl,
                                           int k0, int tid) {
#pragma unroll
    for (int it = 0; it < 4; it++) {
        int idx = tid + it * 256;
        int r = idx >> 3, c = idx & 7;
        uint32_t so = sw128((uint32_t)(r * 128 + c * 16));
        size_t go = (size_t)r * KK + k0 + c * 8;
        cp16(sbase + so, A + go);
        if (TERMS == 3) cp16(sbase + Geo<TERMS>::OFF_ALO + so, Al + go);
        cp16(sbase + Geo<TERMS>::OFF_BHI + so, B + go);
        cp16(sbase + Geo<TERMS>::OFF_BLO + so, Bl + go);
    }
    asm volatile("cp.async.commit_group;" ::: "memory");
}

template <int TERMS>
__device__ __forceinline__ void load_frags(uint32_t stg, int ks,
                                           int warp_m, int warp_n, int lane,
                                           uint32_t (&ahi)[2][4], uint32_t (&alo)[2][4],
                                           uint32_t (&bhi)[8][2], uint32_t (&blo)[8][2]) {
    int row_in = lane & 7, grp = lane >> 3;
#pragma unroll
    for (int mf = 0; mf < 2; mf++) {
        int r = warp_m * 32 + mf * 16 + (grp & 1) * 8 + row_in;
        int kb = ks * 32 + (grp >> 1) * 16;
        uint32_t off = sw128((uint32_t)(r * 128 + kb));
        LDSM4(ahi[mf][0], ahi[mf][1], ahi[mf][2], ahi[mf][3], stg + off);
        if (TERMS == 3)
            LDSM4(alo[mf][0], alo[mf][1], alo[mf][2], alo[mf][3],
                  stg + Geo<TERMS>::OFF_ALO + off);
    }
#pragma unroll
    for (int p = 0; p < 4; p++) {
        int r = warp_n * 64 + p * 16 + (grp >> 1) * 8 + row_in;
        int kb = ks * 32 + (grp & 1) * 16;
        uint32_t off = sw128((uint32_t)(r * 128 + kb));
        uint32_t t0, t1, t2, t3;
        LDSM4(t0, t1, t2, t3, stg + Geo<TERMS>::OFF_BHI + off);
        bhi[2 * p][0] = t0; bhi[2 * p][1] = t1;
        bhi[2 * p + 1][0] = t2; bhi[2 * p + 1][1] = t3;
        LDSM4(t0, t1, t2, t3, stg + Geo<TERMS>::OFF_BLO + off);
        blo[2 * p][0] = t0; blo[2 * p][1] = t1;
        blo[2 * p + 1][0] = t2; blo[2 * p + 1][1] = t3;
    }
}

template <int TERMS, int TILES, int KK, int NTOT>
__global__ void __launch_bounds__(256, 1)
gemm_hs(const __half* __restrict__ Ahi, const __half* __restrict__ Alo,
        const __half* __restrict__ Bhi, const __half* __restrict__ Blo,
        const float* __restrict__ bias, float* __restrict__ C) {
    extern __shared__ char smc[];
    uint32_t sb = s2u(smc);
    int tid = threadIdx.x;
    int wid = tid >> 5, lane = tid & 31;
    int warp_m = wid >> 1, warp_n = wid & 1;
    int bxg = blockIdx.x, by = blockIdx.y;

    constexpr int NC = KK / 64;
    constexpr int TC = TILES * NC;

    const __half* Ah = Ahi + (size_t)(by * 128) * KK;
    const __half* Al = Alo + (size_t)(by * 128) * KK;

    float acc[2][8][4] = {};
    uint32_t ahi[2][2][4], alo[2][2][4], bhi[2][8][2], blo[2][8][2];

    // prologue: 2 global chunks in flight (both belong to tile 0: NC >= 2)
    {
        const __half* Bh0 = Bhi + (size_t)(bxg * TILES * 128) * KK;
        const __half* Bl0 = Blo + (size_t)(bxg * TILES * 128) * KK;
        load_stage<TERMS, KK>(sb + 0 * Geo<TERMS>::STG, Ah, Al, Bh0, Bl0, 0, tid);
        load_stage<TERMS, KK>(sb + 1 * Geo<TERMS>::STG, Ah, Al, Bh0, Bl0, 64, tid);
    }

    for (int tile = 0; tile < TILES; tile++) {
        for (int c = 0; c < NC; c++) {
            int g = tile * NC + c;
            if (g + 1 < TC)
                asm volatile("cp.async.wait_group 1;" ::: "memory");
            else
                asm volatile("cp.async.wait_group 0;" ::: "memory");
            __syncthreads();

            int g2 = g + 2;
            if (g2 < TC) {
                int t2 = g2 / NC, c2 = g2 % NC;
                const __half* Bh2 = Bhi + (size_t)((bxg * TILES + t2) * 128) * KK;
                const __half* Bl2 = Blo + (size_t)((bxg * TILES + t2) * 128) * KK;
                load_stage<TERMS, KK>(sb + (g2 % 3) * Geo<TERMS>::STG,
                                      Ah, Al, Bh2, Bl2, c2 * 64, tid);
            }

            uint32_t stg = sb + (g % 3) * Geo<TERMS>::STG;
            load_frags<TERMS>(stg, 0, warp_m, warp_n, lane, ahi[0], alo[0], bhi[0], blo[0]);
#pragma unroll
            for (int ks = 0; ks < 4; ks++) {
                int cur = ks & 1, nxt = cur ^ 1;
                if (ks < 3)
                    load_frags<TERMS>(stg, ks + 1, warp_m, warp_n, lane,
                                      ahi[nxt], alo[nxt], bhi[nxt], blo[nxt]);
#pragma unroll
                for (int mf = 0; mf < 2; mf++)
#pragma unroll
                    for (int nf = 0; nf < 8; nf++)
                        MMA16816(acc[mf][nf], ahi[cur][mf], bhi[cur][nf]);
#pragma unroll
                for (int mf = 0; mf < 2; mf++)
#pragma unroll
                    for (int nf = 0; nf < 8; nf++)
                        MMA16816(acc[mf][nf], ahi[cur][mf], blo[cur][nf]);
                if (TERMS == 3) {
#pragma unroll
                    for (int mf = 0; mf < 2; mf++)
#pragma unroll
                        for (int nf = 0; nf < 8; nf++)
                            MMA16816(acc[mf][nf], alo[cur][mf], bhi[cur][nf]);
                }
            }
        }

        // tile epilogue: fused bias + fp32 stores, then reset acc.
        // cp.async for the next tile's first chunks are already in flight.
        {
            int col_base = (bxg * TILES + tile) * 128 + warp_n * 64 + (lane & 3) * 2;
            int row_base = by * 128 + warp_m * 32 + (lane >> 2);
#pragma unroll
            for (int mf = 0; mf < 2; mf++)
#pragma unroll
                for (int nf = 0; nf < 8; nf++) {
                    int col = col_base + nf * 8;
                    float b0 = __ldg(bias + col), b1 = __ldg(bias + col + 1);
                    int r0 = row_base + mf * 16;
                    float2 v0 = { acc[mf][nf][0] + b0, acc[mf][nf][1] + b1 };
                    float2 v1 = { acc[mf][nf][2] + b0, acc[mf][nf][3] + b1 };
                    *(float2*)(C + (size_t)r0 * NTOT + col) = v0;
                    *(float2*)(C + (size_t)(r0 + 8) * NTOT + col) = v1;
                }
#pragma unroll
            for (int mf = 0; mf < 2; mf++)
#pragma unroll
                for (int nf = 0; nf < 8; nf++)
#pragma unroll
                    for (int q = 0; q < 4; q++) acc[mf][nf][q] = 0.0f;
        }
    }
}

// ---------------------------------------------------------------------------
// Input projector: x = gelu(hist @ W1 + b1) @ W2 + b2, plus fp16 hi/lo of x
// ---------------------------------------------------------------------------
__global__ void proj_kernel(const float* __restrict__ hist,
                            const float* __restrict__ W1, const float* __restrict__ b1,
                            const float* __restrict__ W2, const float* __restrict__ b2,
                            float* __restrict__ out,
                            __half* __restrict__ ohi, __half* __restrict__ olo) {
    __shared__ float inr[INsz];
    __shared__ float hp[HPsz];
    int row = blockIdx.x;
    int tid = threadIdx.x;

    if (tid < INsz) inr[tid] = hist[(size_t)row * INsz + tid];
    __syncthreads();

    if (tid < HPsz) {
        float a = b1[tid];
#pragma unroll
        for (int i = 0; i < INsz; i++) a += inr[i] * W1[i * HPsz + tid];
        hp[tid] = 0.5f * a * (1.0f + erff(a * 0.70710678118654752440f));
    }
    __syncthreads();

    for (int o = tid; o < Esz; o += 128) {
        float a = b2[o];
#pragma unroll 8
        for (int j = 0; j < HPsz; j++) a += hp[j] * W2[j * Esz + o];
        size_t off = (size_t)row * Esz + o;
        out[off] = a;
        __half h = __float2half_rn(a);
        ohi[off] = h;
        olo[off] = __float2half_rn(a - __half2float(h));
    }
}

// ---------------------------------------------------------------------------
// Block reduce (order-exact match to prior rounds)
// ---------------------------------------------------------------------------
__device__ __forceinline__ float block_reduce_sum(float v) {
    __shared__ float smr[32];
    int lane = threadIdx.x & 31, wid = threadIdx.x >> 5;
#pragma unroll
    for (int o = 16; o > 0; o >>= 1) v += __shfl_xor_sync(0xffffffffu, v, o);
    __syncthreads();
    if (lane == 0) smr[wid] = v;
    __syncthreads();
    if (wid == 0) {
        v = (lane < (int)(blockDim.x >> 5)) ? smr[lane] : 0.0f;
#pragma unroll
        for (int o = 16; o > 0; o >>= 1) v += __shfl_xor_sync(0xffffffffu, v, o);
        if (lane == 0) smr[0] = v;
    }
    __syncthreads();
    return smr[0];
}

// ---------------------------------------------------------------------------
// LN stats: one block per row, same reduction tree as before (bit-identical
// mean/rstd). Writes only (mean, rstd) per row.
// ---------------------------------------------------------------------------
template <int N, int NTHR>
__global__ void ln_stats(const float* __restrict__ x,
                         float* __restrict__ mean, float* __restrict__ rstd) {
    size_t row = blockIdx.x;
    const float4* p = (const float4*)(x + row * (size_t)N);
    int tid = threadIdx.x;

    float4 v = p[tid];
    float s = v.x + v.y + v.z + v.w;
    float m = block_reduce_sum(s) * (1.0f / N);

    float dx = v.x - m, dy = v.y - m, dz = v.z - m, dw = v.w - m;
    float var = block_reduce_sum(dx * dx + dy * dy + dz * dz + dw * dw) * (1.0f / N);
    float inv = 1.0f / sqrtf(var + 1e-5f);

    if (tid == 0) { mean[row] = m; rstd[row] = inv; }
}

// ---------------------------------------------------------------------------
// LIF apply (spike emit): thread per (b, channel), normalizes on the fly.
// ---------------------------------------------------------------------------
__global__ void lif_apply(const float* __restrict__ h,
                          const float* __restrict__ mean, const float* __restrict__ rstd,
                          const float* __restrict__ gamma, const float* __restrict__ beta,
                          __half* __restrict__ spk, int C) {
    int idx = blockIdx.x * blockDim.x + threadIdx.x;
    if (idx >= Bsz * C) return;
    int b = idx / C, j = idx % C;
    float gg = gamma[j], bb = beta[j];
    float v = 0.0f;
    size_t base = (size_t)b * Tsz * C + j;
    int rbase = b * Tsz;
#pragma unroll 4
    for (int t = 0; t < Tsz; t++) {
        size_t o = base + (size_t)t * C;
        float xi = h[o];
        float m = __ldg(mean + rbase + t);
        float inv = __ldg(rstd + rbase + t);
        float n = (xi - m) * inv * gg + bb;
        v = v + (n - v) * 0.5f;
        float sp = 0.0f;
        if (v >= 1.0f) { sp = 1.0f; v = 0.0f; }
        spk[o] = __float2half_rn(sp);
    }
}

// LIF apply + residual add + sparse split refresh
__global__ void lifadd_apply(const float* __restrict__ h,
                             const float* __restrict__ mean, const float* __restrict__ rstd,
                             const float* __restrict__ gamma, const float* __restrict__ beta,
                             float* __restrict__ x, __half* __restrict__ xhi,
                             __half* __restrict__ xlo, int C) {
    int idx = blockIdx.x * blockDim.x + threadIdx.x;
    if (idx >= Bsz * C) return;
    int b = idx / C, j = idx % C;
    float gg = gamma[j], bb = beta[j];
    float v = 0.0f;
    size_t base = (size_t)b * Tsz * C + j;
    int rbase = b * Tsz;
#pragma unroll 4
    for (int t = 0; t < Tsz; t++) {
        size_t o = base + (size_t)t * C;
        float xi = h[o];
        float m = __ldg(mean + rbase + t);
        float inv = __ldg(rstd + rbase + t);
        float n = (xi - m) * inv * gg + bb;
        v = v + (n - v) * 0.5f;
        if (v >= 1.0f) {
            v = 0.0f;
            float xv = x[o] + 1.0f;
            x[o] = xv;
            __half hh = __float2half_rn(xv);
            xhi[o] = hh;
            xlo[o] = __float2half_rn(xv - __half2float(hh));
        }
    }
}

// Extract last timestep
__global__ void last_kernel(const float* __restrict__ x, float* __restrict__ out) {
    int i = blockIdx.x * blockDim.x + threadIdx.x;
    if (i < Bsz * Esz) {
        int b = i / Esz, e = i % Esz;
        out[i] = x[((size_t)b * Tsz + (Tsz - 1)) * Esz + e];
    }
}

// ---------------------------------------------------------------------------
extern "C" void kernel_launch(void* const* d_in, const int* in_sizes, int n_in,
                              void* d_out, int out_size) {
    const float* hist  = (const float*)d_in[0];
    const float* pW1   = (const float*)d_in[1];
    const float* pb1   = (const float*)d_in[2];
    const float* pW2   = (const float*)d_in[3];
    const float* pb2   = (const float*)d_in[4];
    const float* fc1_w = (const float*)d_in[5];
    const float* fc1_b = (const float*)d_in[6];
    const float* ln1_g = (const float*)d_in[7];
    const float* ln1_b = (const float*)d_in[8];
    const float* fc2_w = (const float*)d_in[9];
    const float* fc2_b = (const float*)d_in[10];
    const float* ln2_g = (const float*)d_in[11];
    const float* ln2_b = (const float*)d_in[12];

    float *x, *h1, *h2, *mean, *rstd;
    __half *xhi, *xlo, *spk, *w1hi, *w1lo, *w2hi, *w2lo;
    cudaGetSymbolAddress((void**)&x,    g_x);
    cudaGetSymbolAddress((void**)&h1,   g_h1);
    cudaGetSymbolAddress((void**)&h2,   g_h2);
    cudaGetSymbolAddress((void**)&mean, g_mean);
    cudaGetSymbolAddress((void**)&rstd, g_rstd);
    cudaGetSymbolAddress((void**)&xhi,  g_xhi);
    cudaGetSymbolAddress((void**)&xlo,  g_xlo);
    cudaGetSymbolAddress((void**)&spk,  g_spk);
    cudaGetSymbolAddress((void**)&w1hi, g_w1hi);
    cudaGetSymbolAddress((void**)&w1lo, g_w1lo);
    cudaGetSymbolAddress((void**)&w2hi, g_w2hi);
    cudaGetSymbolAddress((void**)&w2lo, g_w2lo);

    auto* gk1 = gemm_hs<3, 4, Esz, Hsz>;   // GEMM1: K=512, N=1024, 4 tiles/CTA
    auto* gk2 = gemm_hs<2, 2, Hsz, Esz>;   // GEMM2: K=1024, N=512, 2 tiles/CTA
    cudaFuncSetAttribute(gk1, cudaFuncAttributeMaxDynamicSharedMemorySize, Geo<3>::TOT);
    cudaFuncSetAttribute(gk2, cudaFuncAttributeMaxDynamicSharedMemorySize, Geo<2>::TOT);

    split_w<<<dim3((Esz * Hsz + 255) / 256, Dsz), 256>>>(fc1_w, w1hi, w1lo, Esz, Hsz);
    split_w<<<dim3((Hsz * Esz + 255) / 256, Dsz), 256>>>(fc2_w, w2hi, w2lo, Hsz, Esz);

    proj_kernel<<<ROWS, 128>>>(hist, pW1, pb1, pW2, pb2, x, xhi, xlo);

    for (int d = 0; d < Dsz; d++) {
        size_t o1 = (size_t)d * Hsz * Esz;   // Wt1 [H][E] per layer
        size_t o2 = (size_t)d * Esz * Hsz;   // Wt2 [E][H] per layer

        gk1<<<dim3(Hsz / 128 / 4, ROWS / 128), 256, Geo<3>::TOT>>>(
            xhi, xlo, w1hi + o1, w1lo + o1, fc1_b + d * Hsz, h1);
        ln_stats<Hsz, 256><<<ROWS, 256>>>(h1, mean, rstd);
        lif_apply<<<(Bsz * Hsz + 255) / 256, 256>>>(
            h1, mean, rstd, ln1_g + d * Hsz, ln1_b + d * Hsz, spk, Hsz);

        gk2<<<dim3(Esz / 128 / 2, ROWS / 128), 256, Geo<2>::TOT>>>(
            spk, spk, w2hi + o2, w2lo + o2, fc2_b + d * Esz, h2);
        ln_stats<Esz, 128><<<ROWS, 128>>>(h2, mean, rstd);
        lifadd_apply<<<(Bsz * Esz + 255) / 256, 256>>>(
            h2, mean, rstd, ln2_g + d * Esz, ln2_b + d * Esz, x, xhi, xlo, Esz);
    }

    last_kernel<<<(Bsz * Esz + 255) / 256, 256>>>(x, (float*)d_out);
}